// round 2
// baseline (speedup 1.0000x reference)
#include <cuda_runtime.h>

// Shapes: x_ref, x : [B=4, C=3, H=512, W=512] float32
// Output: out [4,3,512,512] f32 (3145728 elems) then best_shifts [4,2] as floats (8 elems)

#define NIMG   12          // B*C
#define HH     512
#define WW     512
#define PADW   520         // 4-col halo each side
#define PADW4  (PADW/4)    // 130 float4 per padded row
#define NSHIFT 81
#define IMG_ELEMS (HH*WW)          // 262144
#define OUT_IMG   (NIMG*IMG_ELEMS) // 3145728

__device__ float4 g_refpad[NIMG * HH * PADW4];   // ~12.8 MB padded ref
__device__ float  g_sims[4 * NSHIFT];
__device__ int2   g_best[4];

// ---------------------------------------------------------------------------
// Phase 0: build zero-padded ref copy + zero sims accumulators
// ---------------------------------------------------------------------------
__global__ void prep_kernel(const float* __restrict__ xref) {
    int idx = blockIdx.x * blockDim.x + threadIdx.x;
    if (idx < 4 * NSHIFT) g_sims[idx] = 0.0f;
    const int total = NIMG * HH * PADW;
    if (idx >= total) return;
    int pcol = idx % PADW;
    int row  = (idx / PADW) % HH;
    int img  = idx / (PADW * HH);
    int col  = pcol - 4;
    float v = 0.0f;
    if ((unsigned)col < (unsigned)WW)
        v = xref[(img * HH + row) * WW + col];
    ((float*)g_refpad)[(img * HH + row) * PADW + pcol] = v;
}

// ---------------------------------------------------------------------------
// Phase 1: 81-shift correlation. Each thread: 8 cols x 4 rows of one image,
// 81 register accumulators. 2592 FMAs per thread.
// Grid: 12 imgs * 128 rowgroups * 64 strips = 98304 threads = 384 blocks x 256
// ---------------------------------------------------------------------------
__global__ void __launch_bounds__(256) corr_kernel(const float* __restrict__ x) {
    int gid    = blockIdx.x * 256 + threadIdx.x;
    int img    = gid >> 13;        // / 8192   (uniform per block: 32 blocks/img)
    int within = gid & 8191;
    int rowgrp = within >> 6;      // / 64
    int strip  = within & 63;
    int r0     = rowgrp * 4;
    int j0     = strip * 8;
    int b      = img / 3;

    float acc[NSHIFT];
#pragma unroll
    for (int s = 0; s < NSHIFT; s++) acc[s] = 0.0f;

    const float4* xp4 = (const float4*)x + (size_t)img * HH * (WW / 4);
    const float4* rbase = g_refpad + (size_t)img * HH * PADW4 + (j0 >> 2);

#pragma unroll
    for (int r = 0; r < 4; r++) {
        int a = r0 + r;
        float4 xa = xp4[a * (WW / 4) + (j0 >> 2)];
        float4 xb = xp4[a * (WW / 4) + (j0 >> 2) + 1];
        float xv[8] = {xa.x, xa.y, xa.z, xa.w, xb.x, xb.y, xb.z, xb.w};
#pragma unroll
        for (int dx = 0; dx < 9; dx++) {
            int ar = a + dx - 4;
            if ((unsigned)ar < (unsigned)HH) {
                const float4* rp = rbase + ar * PADW4;
                float4 q0 = rp[0], q1 = rp[1], q2 = rp[2], q3 = rp[3];
                float rv[16] = {q0.x, q0.y, q0.z, q0.w, q1.x, q1.y, q1.z, q1.w,
                                q2.x, q2.y, q2.z, q2.w, q3.x, q3.y, q3.z, q3.w};
#pragma unroll
                for (int p = 0; p < 8; p++) {
#pragma unroll
                    for (int dy = 0; dy < 9; dy++) {
                        acc[dx * 9 + dy] += xv[p] * rv[p + dy];
                    }
                }
            }
        }
    }

    // warp butterfly reduce each of 81 partials, then spread atomics over lanes
    int lane = threadIdx.x & 31;
#pragma unroll
    for (int s = 0; s < NSHIFT; s++) {
        float v = acc[s];
        v += __shfl_xor_sync(0xffffffffu, v, 16);
        v += __shfl_xor_sync(0xffffffffu, v, 8);
        v += __shfl_xor_sync(0xffffffffu, v, 4);
        v += __shfl_xor_sync(0xffffffffu, v, 2);
        v += __shfl_xor_sync(0xffffffffu, v, 1);
        if (lane == (s & 31)) atomicAdd(&g_sims[b * NSHIFT + s], v);
    }
}

// ---------------------------------------------------------------------------
// Phase 2: argmax per batch (first-max tie-break, matching jnp.argmax)
// ---------------------------------------------------------------------------
__global__ void argmax_kernel(float* __restrict__ d_out, int out_size) {
    int w = threadIdx.x >> 5;
    int lane = threadIdx.x & 31;
    if (w >= 4) return;
    float bv = -3.0e38f;
    int bi = NSHIFT;
    for (int s = lane; s < NSHIFT; s += 32) {
        float v = g_sims[w * NSHIFT + s];
        if (v > bv || (v == bv && s < bi)) { bv = v; bi = s; }
    }
#pragma unroll
    for (int off = 16; off; off >>= 1) {
        float ov = __shfl_xor_sync(0xffffffffu, bv, off);
        int   oi = __shfl_xor_sync(0xffffffffu, bi, off);
        if (ov > bv || (ov == bv && oi < bi)) { bv = ov; bi = oi; }
    }
    if (lane == 0) {
        int sx = bi / 9 - 4;
        int sy = bi % 9 - 4;
        g_best[w] = make_int2(sx, sy);
        if (out_size >= OUT_IMG + 8) {
            d_out[OUT_IMG + w * 2 + 0] = (float)sx;
            d_out[OUT_IMG + w * 2 + 1] = (float)sy;
        }
    }
}

// ---------------------------------------------------------------------------
// Phase 3: apply best shift (zero-fill wrapped rows/cols)
// ---------------------------------------------------------------------------
__global__ void apply_kernel(const float* __restrict__ x, float* __restrict__ out) {
    int gid = blockIdx.x * blockDim.x + threadIdx.x;
    if (gid >= OUT_IMG) return;
    int j   = gid & 511;
    int i   = (gid >> 9) & 511;
    int img = gid >> 18;
    int b   = img / 3;
    int2 s  = g_best[b];
    int si = i - s.x;
    int sj = j - s.y;
    float v = 0.0f;
    if ((unsigned)si < (unsigned)HH && (unsigned)sj < (unsigned)WW)
        v = x[(img << 18) + (si << 9) + sj];
    out[gid] = v;
}

// ---------------------------------------------------------------------------
extern "C" void kernel_launch(void* const* d_in, const int* in_sizes, int n_in,
                              void* d_out, int out_size) {
    const float* x_ref = (const float*)d_in[0];
    const float* x     = (const float*)d_in[1];
    float* out = (float*)d_out;

    // Phase 0: pad ref + zero sims
    {
        int total = NIMG * HH * PADW;
        int blocks = (total + 255) / 256;
        prep_kernel<<<blocks, 256>>>(x_ref);
    }
    // Phase 1: correlation
    corr_kernel<<<384, 256>>>(x);
    // Phase 2: argmax
    argmax_kernel<<<1, 128>>>(out, out_size);
    // Phase 3: apply shift
    apply_kernel<<<OUT_IMG / 256, 256>>>(x, out);
}

// round 4
// speedup vs baseline: 3.3031x; 3.3031x over previous
#include <cuda_runtime.h>

// x_ref, x : [B=4, C=3, H=512, W=512] float32
// out: [4,3,512,512] f32 (3145728) then best_shifts [4,2] as floats (8)

#define NIMG   12
#define HH     512
#define WW     512
#define PROWS  520          // 4-row halo each side
#define PADW   520          // 4-col halo each side
#define PADW4  (PADW/4)     // 130
#define NSHIFT 81
#define IMG_ELEMS (HH*WW)
#define OUT_IMG   (NIMG*IMG_ELEMS)   // 3145728

__device__ float4 g_refpad[NIMG * PROWS * PADW4];   // ~13 MB zero-padded ref
__device__ float  g_sims[4 * NSHIFT];
__device__ int2   g_best[4];

// ---------------------------------------------------------------------------
// Phase 0: zero-padded ref copy (rows AND cols padded) + zero sims.
// One float4 store per thread.
// ---------------------------------------------------------------------------
__global__ void __launch_bounds__(256) prep_kernel(const float* __restrict__ xref) {
    int idx = blockIdx.x * 256 + threadIdx.x;
    if (idx < 4 * NSHIFT) g_sims[idx] = 0.0f;
    const int total4 = NIMG * PROWS * PADW4;     // 811200
    if (idx >= total4) return;
    int pc4 = idx % PADW4;
    int pr  = (idx / PADW4) % PROWS;
    int img = idx / (PADW4 * PROWS);
    int srow = pr - 4;
    float4 v = make_float4(0.f, 0.f, 0.f, 0.f);
    if ((unsigned)srow < (unsigned)HH) {
        const float* src = xref + ((size_t)img * HH + srow) * WW;
        int c0 = pc4 * 4 - 4;
        float* vp = (float*)&v;
#pragma unroll
        for (int k = 0; k < 4; k++) {
            int c = c0 + k;
            if ((unsigned)c < (unsigned)WW) vp[k] = __ldg(src + c);
        }
    }
    g_refpad[idx] = v;
}

// ---------------------------------------------------------------------------
// Phase 1: 81-shift correlation. Thread: 4 rows x 8 cols, dx-outer loop with
// only 9 live accumulators. 2592 FMAs/thread. Block smem reduction.
// Grid: 12 imgs * 32 blocks; block = 256 thr = 4 rowgroups x 64 strips.
// ---------------------------------------------------------------------------
__global__ void __launch_bounds__(256) corr_kernel(const float* __restrict__ x) {
    __shared__ float ssum[NSHIFT];
    if (threadIdx.x < NSHIFT) ssum[threadIdx.x] = 0.0f;
    __syncthreads();

    int img   = blockIdx.x >> 5;                 // 32 blocks per image
    int strip = threadIdx.x & 63;
    int rgrp  = ((blockIdx.x & 31) << 2) + (threadIdx.x >> 6);
    int a0    = rgrp * 4;
    int j0    = strip * 8;
    int b     = img / 3;
    int lane  = threadIdx.x & 31;

    // preload x strip: 4 rows x 8 cols (32 regs)
    const float4* xp4 = (const float4*)x + (size_t)img * HH * (WW / 4);
    float xv[32];
#pragma unroll
    for (int r = 0; r < 4; r++) {
        float4 m0 = __ldg(xp4 + (a0 + r) * (WW / 4) + (j0 >> 2));
        float4 m1 = __ldg(xp4 + (a0 + r) * (WW / 4) + (j0 >> 2) + 1);
        xv[r * 8 + 0] = m0.x; xv[r * 8 + 1] = m0.y;
        xv[r * 8 + 2] = m0.z; xv[r * 8 + 3] = m0.w;
        xv[r * 8 + 4] = m1.x; xv[r * 8 + 5] = m1.y;
        xv[r * 8 + 6] = m1.z; xv[r * 8 + 7] = m1.w;
    }

    // running row pointer: first ref row touched is padded row a0 (dx=0,r=0)
    const float4* rrow = g_refpad + (size_t)img * PROWS * PADW4
                         + (size_t)a0 * PADW4 + (j0 >> 2);

#pragma unroll 1
    for (int dx = 0; dx < 9; dx++) {
        float acc[9];
#pragma unroll
        for (int d = 0; d < 9; d++) acc[d] = 0.0f;

#pragma unroll
        for (int r = 0; r < 4; r++) {
            const float4* rp = rrow + r * PADW4;
            float4 q0 = rp[0], q1 = rp[1], q2 = rp[2], q3 = rp[3];
            float rv[16] = {q0.x, q0.y, q0.z, q0.w, q1.x, q1.y, q1.z, q1.w,
                            q2.x, q2.y, q2.z, q2.w, q3.x, q3.y, q3.z, q3.w};
#pragma unroll
            for (int p = 0; p < 8; p++) {
#pragma unroll
                for (int d = 0; d < 9; d++) {
                    acc[d] += xv[r * 8 + p] * rv[p + d];
                }
            }
        }

        // warp butterfly per dy, then one-lane atomic into block smem
#pragma unroll
        for (int d = 0; d < 9; d++) {
            float v = acc[d];
            v += __shfl_xor_sync(0xffffffffu, v, 16);
            v += __shfl_xor_sync(0xffffffffu, v, 8);
            v += __shfl_xor_sync(0xffffffffu, v, 4);
            v += __shfl_xor_sync(0xffffffffu, v, 2);
            v += __shfl_xor_sync(0xffffffffu, v, 1);
            int s = dx * 9 + d;
            if (lane == (s & 31)) atomicAdd(&ssum[s], v);
        }
        rrow += PADW4;   // next dx shifts the ref window down one row
    }

    __syncthreads();
    if (threadIdx.x < NSHIFT)
        atomicAdd(&g_sims[b * NSHIFT + threadIdx.x], ssum[threadIdx.x]);
}

// ---------------------------------------------------------------------------
// Phase 2: argmax per batch (first-max tie-break, matching jnp.argmax)
// ---------------------------------------------------------------------------
__global__ void argmax_kernel(float* __restrict__ d_out, int out_size) {
    int w = threadIdx.x >> 5;
    int lane = threadIdx.x & 31;
    if (w >= 4) return;
    float bv = -3.0e38f;
    int bi = NSHIFT;
    for (int s = lane; s < NSHIFT; s += 32) {
        float v = g_sims[w * NSHIFT + s];
        if (v > bv || (v == bv && s < bi)) { bv = v; bi = s; }
    }
#pragma unroll
    for (int off = 16; off; off >>= 1) {
        float ov = __shfl_xor_sync(0xffffffffu, bv, off);
        int   oi = __shfl_xor_sync(0xffffffffu, bi, off);
        if (ov > bv || (ov == bv && oi < bi)) { bv = ov; bi = oi; }
    }
    if (lane == 0) {
        int sx = bi / 9 - 4;
        int sy = bi % 9 - 4;
        g_best[w] = make_int2(sx, sy);
        if (out_size >= OUT_IMG + 8) {
            d_out[OUT_IMG + w * 2 + 0] = (float)sx;
            d_out[OUT_IMG + w * 2 + 1] = (float)sy;
        }
    }
}

// ---------------------------------------------------------------------------
// Phase 3: apply best shift. float4 stores, scalar loads (sy-misaligned).
// ---------------------------------------------------------------------------
__global__ void __launch_bounds__(256) apply_kernel(const float* __restrict__ x,
                                                    float* __restrict__ out) {
    int t = blockIdx.x * 256 + threadIdx.x;      // float4 index
    int base = t << 2;
    if (base >= OUT_IMG) return;
    int j0  = base & 511;
    int i   = (base >> 9) & 511;
    int img = base >> 18;
    int b   = img / 3;
    int2 s  = g_best[b];
    int si  = i - s.x;
    float4 v = make_float4(0.f, 0.f, 0.f, 0.f);
    if ((unsigned)si < (unsigned)HH) {
        const float* src = x + ((size_t)img << 18) + (si << 9);
        int sj = j0 - s.y;
        float* vp = (float*)&v;
#pragma unroll
        for (int k = 0; k < 4; k++) {
            int c = sj + k;
            if ((unsigned)c < (unsigned)WW) vp[k] = __ldg(src + c);
        }
    }
    ((float4*)out)[t] = v;
}

// ---------------------------------------------------------------------------
extern "C" void kernel_launch(void* const* d_in, const int* in_sizes, int n_in,
                              void* d_out, int out_size) {
    const float* x_ref = (const float*)d_in[0];
    const float* x     = (const float*)d_in[1];
    float* out = (float*)d_out;

    {
        int total4 = NIMG * PROWS * PADW4;
        prep_kernel<<<(total4 + 255) / 256, 256>>>(x_ref);
    }
    corr_kernel<<<384, 256>>>(x);
    argmax_kernel<<<1, 128>>>(out, out_size);
    apply_kernel<<<(OUT_IMG / 4 + 255) / 256, 256>>>(x, out);
}